// round 5
// baseline (speedup 1.0000x reference)
#include <cuda_runtime.h>
#include <cstdint>

// OR-tree reduction over rows of a (ROWS, 1024) float32 0/1 matrix.
// Reference pairwise-sum >= 0.5 tree == any(x >= 0.5) over the row.
//
// R2-R4 post-mortem: time was pinned at ~6.1us because only 2048 warps were
// live (occ ~18%) -> too little memory-level parallelism for 65536 scattered
// 128B lines at ~600cyc DRAM latency (eff BW capped ~1.36 TB/s).
//
// This kernel: 8 ROWS PER WARP. Lane L probes row (L>>2), float4 (L&3):
//  - one LDG.128 per lane, 64B contiguous per row, 16 floats probed per row
//  - 8192 warps (4x more), ~55/SM -> nearly all lines in flight at once
//  - per-row resolve prob 1 - 2^-16 -> expected ~1 rescue in the whole grid
//  - ballot combines each 4-lane group; lanes L%4==0 store 8 consecutive
//    floats per warp (coalesced 32B)
// Rescue: warp-uniform loop, each unresolved group rescans its row in
// batches of 32 float4 (lane-strided, 8 loads per lane per batch), ballot +
// early exit per batch. Worst case = correct full scan.
// Assumes rows % 8 == 0 (rows = 65536 here).

static constexpr int COLS = 1024;
static constexpr int F4_PER_ROW = COLS / 4; // 256
static constexpr unsigned FULL = 0xffffffffu;

__device__ __forceinline__ bool any_ge_half(const float4 v) {
    return (v.x >= 0.5f) | (v.y >= 0.5f) | (v.z >= 0.5f) | (v.w >= 0.5f);
}

__global__ void __launch_bounds__(256) vec_or_tree_kernel(
    const float4* __restrict__ x,
    float* __restrict__ out,
    int rows)
{
    const int warp = (blockIdx.x * blockDim.x + threadIdx.x) >> 5;
    const int lane = threadIdx.x & 31;
    const int rbase = warp * 8;
    if (rbase >= rows) return;

    const int rlocal = lane >> 2;   // 0..7: which of the 8 rows
    const int f4i    = lane & 3;    // 0..3: which float4 within the probe
    const int row    = rbase + rlocal;

    const float4* __restrict__ rp = x + (size_t)row * F4_PER_ROW;

    // Probe: one LDG.128 per lane; 4 lanes cover 64B of each row.
    const float4 v = rp[f4i];
    bool fired = any_ge_half(v);

    // Combine within each 4-lane group via ballot.
    unsigned bal = __ballot_sync(FULL, fired);
    unsigned grp = (bal >> (lane & 28)) & 0xFu;
    bool done = (grp != 0);

    // Rescue (expected ~1 group in the entire grid): rescan row in batches
    // of 32 float4 (128 floats) per exposure, warp-uniform control flow.
    if (__any_sync(FULL, !done)) {
        #pragma unroll 1
        for (int base = 0; base < F4_PER_ROW; base += 32) {
            bool f = false;
            if (!done) {
                #pragma unroll
                for (int j = 0; j < 8; ++j) {
                    f |= any_ge_half(rp[base + f4i + 4 * j]);
                }
            }
            const unsigned b2 = __ballot_sync(FULL, f);
            grp |= (b2 >> (lane & 28)) & 0xFu;
            done = (grp != 0);
            if (__all_sync(FULL, done)) break;
        }
    }

    // Lanes 0,4,...,28 write 8 consecutive outputs (coalesced 32B).
    if ((lane & 3) == 0) out[row] = done ? 1.0f : 0.0f;
}

extern "C" void kernel_launch(void* const* d_in, const int* in_sizes, int n_in,
                              void* d_out, int out_size)
{
    const float4* x = (const float4*)d_in[0];
    float* out = (float*)d_out;
    const int rows = in_sizes[0] / COLS;   // 65536 (multiple of 8)

    const int threads = 256;                         // 8 warps/block
    const int rows_per_block = (threads / 32) * 8;   // 64
    const int blocks = (rows + rows_per_block - 1) / rows_per_block;  // 1024
    vec_or_tree_kernel<<<blocks, threads>>>(x, out, rows);
}

// round 6
// speedup vs baseline: 1.0947x; 1.0947x over previous
#include <cuda_runtime.h>
#include <cstdint>

// OR-tree reduction over rows of a (ROWS, 1024) float32 0/1 matrix.
// Reference pairwise-sum >= 0.5 tree == any(x >= 0.5) over the row.
//
// R2-R5 post-mortem: throughput pinned at 1.36 TB/s independent of load
// count, MLP, and occupancy. All probes hit byte offset 0 of 4KB-strided
// rows -> identical address bits [0:12) -> suspected HBM channel/bank hash
// aliasing (only ~1/6 of channels active). R1, whose accesses varied bits
// 7-8, sustained 3.1 TB/s.
//
// Fix vs R5 (one variable changed): row r's probe reads the 128B line at
// byte offset (r & 31)*128 within the row, sweeping address bits 7-11
// across rows to spread lines over all channels/banks. The OR probe is
// position-independent; the (prob ~2^-16 per row) rescue still full-scans
// the row, so correctness holds for any input.
//
// Structure (from R5): 8 rows/warp, lane L -> row (L>>2), float4 (L&3);
// one LDG.128 per lane (64B probed per row), ballot per 4-lane group,
// coalesced 8-float store per warp. rows % 8 == 0.

static constexpr int COLS = 1024;
static constexpr int F4_PER_ROW = COLS / 4; // 256
static constexpr unsigned FULL = 0xffffffffu;

__device__ __forceinline__ bool any_ge_half(const float4 v) {
    return (v.x >= 0.5f) | (v.y >= 0.5f) | (v.z >= 0.5f) | (v.w >= 0.5f);
}

__global__ void __launch_bounds__(256) vec_or_tree_kernel(
    const float4* __restrict__ x,
    float* __restrict__ out,
    int rows)
{
    const int warp = (blockIdx.x * blockDim.x + threadIdx.x) >> 5;
    const int lane = threadIdx.x & 31;
    const int rbase = warp * 8;
    if (rbase >= rows) return;

    const int rlocal = lane >> 2;   // 0..7: which of the 8 rows
    const int f4i    = lane & 3;    // 0..3: float4 within the probed line
    const int row    = rbase + rlocal;

    const float4* __restrict__ rp = x + (size_t)row * F4_PER_ROW;

    // De-aliased probe: 128B line at float4 index (row & 31) * 8.
    // Varies address bits 7-11 across rows -> spreads HBM channels/banks.
    const int poff = (row & 31) * 8;
    const float4 v = rp[poff + f4i];
    bool fired = any_ge_half(v);

    // Combine within each 4-lane group via ballot.
    unsigned bal = __ballot_sync(FULL, fired);
    unsigned grp = (bal >> (lane & 28)) & 0xFu;
    bool done = (grp != 0);

    // Rescue (expected ~1 group in the whole grid): warp-uniform batched
    // full rescan of the row, early exit per 32-float4 batch.
    if (__any_sync(FULL, !done)) {
        #pragma unroll 1
        for (int base = 0; base < F4_PER_ROW; base += 32) {
            bool f = false;
            if (!done) {
                #pragma unroll
                for (int j = 0; j < 8; ++j) {
                    f |= any_ge_half(rp[base + f4i + 4 * j]);
                }
            }
            const unsigned b2 = __ballot_sync(FULL, f);
            grp |= (b2 >> (lane & 28)) & 0xFu;
            done = (grp != 0);
            if (__all_sync(FULL, done)) break;
        }
    }

    // Lanes 0,4,...,28 write 8 consecutive outputs (coalesced 32B).
    if ((lane & 3) == 0) out[row] = done ? 1.0f : 0.0f;
}

extern "C" void kernel_launch(void* const* d_in, const int* in_sizes, int n_in,
                              void* d_out, int out_size)
{
    const float4* x = (const float4*)d_in[0];
    float* out = (float*)d_out;
    const int rows = in_sizes[0] / COLS;   // 65536 (multiple of 8)

    const int threads = 256;                         // 8 warps/block
    const int rows_per_block = (threads / 32) * 8;   // 64
    const int blocks = (rows + rows_per_block - 1) / rows_per_block;  // 1024
    vec_or_tree_kernel<<<blocks, threads>>>(x, out, rows);
}